// round 2
// baseline (speedup 1.0000x reference)
#include <cuda_runtime.h>
#include <math.h>

// Celerite (single-term Exp kernel, multiband amplitudes) log-likelihood.
//   Pass 1 (k1): per-segment composition of the cS Mobius map, expressed in
//                shifted coords w = 1/sigma2 - cS (all-positive matrices).
//   Pass 2 (k2): single-block scan of segment matrices -> incoming w per segment.
//   Pass 3 (k3): exact in-segment recurrence from w_in; exports affine (A,B)
//                for the cg carry and quadratic (Q0,Qcd,Q2) for the quad sum.
//   Pass 4 (k4): single-block affine scan + quadratic evaluation + reduction.
//
// w-step: w' = e2*( c*(1-p2) + p2*w ) / ( Dt + U^2 p2 w ),  Dt = e2 + U*u*(1-p2)
// where e2 = yerr^2, U = sigma2*u, c = 1/sigma2.  D = Dt + U^2 p2 w.
// W = (u*(1-p2) + U p2 w)/D ;  cg' = p(1-WU) cg + W y ; z = y - U p cg_prev.

#define SEG_LEN 64
#define MAX_SEG 65536
#define SCAN_T  1024

__device__ float4 g_segM[MAX_SEG];   // w-space matrix per segment {r00,r01,r10,r11}
__device__ float  g_win[MAX_SEG];    // incoming w per segment
__device__ float4 g_segA[MAX_SEG];   // {A, B, sum(logD), 0}
__device__ float4 g_segQ[MAX_SEG];   // {Q0, Qcd, Q2, 0}

__device__ __forceinline__ float pick_amp(int b, float a1, float a2, float a3) {
    float u = 1.0f;
    u = (b == 1) ? a1 : u;
    u = (b == 2) ? a2 : u;
    u = (b == 3) ? a3 : u;
    return u;
}

__device__ __forceinline__ float fast_rcp(float x) { return __fdividef(1.0f, x); }

// compose R <- M * R (M applied after R), then normalize so r11 = 1.
// All entries nonnegative -> no cancellation.
__device__ __forceinline__ void mob_compose_norm(
    float& r00, float& r01, float& r10, float& r11,
    float m00, float m01, float m10, float m11)
{
    float n00 = fmaf(m00, r00, m01 * r10);
    float n01 = fmaf(m00, r01, m01 * r11);
    float n10 = fmaf(m10, r00, m11 * r10);
    float n11 = fmaf(m10, r01, m11 * r11);
    float rn  = fast_rcp(n11);
    r00 = n00 * rn; r01 = n01 * rn; r10 = n10 * rn; r11 = 1.0f;
}

// one w-space element step; matrix pre-scaled by 1/Dt (off the carry chain)
__device__ __forceinline__ void mob_elem(
    float& r00, float& r01, float& r10, float& r11,
    float ti, int b, float ye, float& prev_t, int gi,
    float sigma2, float inv_sigma2, float two_nie, float a1, float a2, float a3)
{
    float u  = pick_amp(b, a1, a2, a3);
    float U  = sigma2 * u;
    float UV = U * u;                    // sigma2 * u^2
    float e2 = ye * ye;
    float omp2 = (gi == 0) ? 1.0f : -expm1f(two_nie * (ti - prev_t)); // 1 - p^2, accurate
    float p2   = 1.0f - omp2;
    prev_t = ti;
    float Dt    = fmaf(UV, omp2, e2);    // e2 + UV*(1-p2)  > 0
    float invDt = fast_rcp(Dt);
    float m00 = p2 * e2 * invDt;
    float m01 = inv_sigma2 * e2 * omp2 * invDt;
    float m10 = U * U * p2 * invDt;
    // m11 = 1
    float n00 = fmaf(m00, r00, m01 * r10);
    float n01 = fmaf(m00, r01, m01 * r11);
    float n10 = fmaf(m10, r00, r10);
    float n11 = fmaf(m10, r01, r11);
    r00 = n00; r01 = n01; r10 = n10; r11 = n11;
}

// ------------------- Kernel 1: per-segment w-map composition -------------------
__global__ void __launch_bounds__(256) k1_mobius(
    const float* __restrict__ t, const int* __restrict__ band,
    const float* __restrict__ yerr,
    const float* __restrict__ lad, const float* __restrict__ lkp,
    int N, int nseg)
{
    int seg = blockIdx.x * blockDim.x + threadIdx.x;
    if (seg >= nseg) return;

    float sigma2 = expf(2.0f * lkp[0]);
    float inv_sigma2 = 1.0f / sigma2;
    float two_nie = -2.0f / expf(lkp[1]);
    float a1 = expf(lad[0]), a2 = expf(lad[1]), a3 = expf(lad[2]);

    int start = seg * SEG_LEN;
    int end   = min(start + SEG_LEN, N);
    float prev_t = (start > 0) ? __ldg(t + start - 1) : 0.0f;

    float r00 = 1.f, r01 = 0.f, r10 = 0.f, r11 = 1.f;

    if (end - start == SEG_LEN) {
        const float4* t4p = (const float4*)(t + start);
        const int4*   b4p = (const int4*)(band + start);
        const float4* e4p = (const float4*)(yerr + start);
        #pragma unroll 1
        for (int blk = 0; blk < SEG_LEN / 4; ++blk) {
            float4 t4 = __ldg(t4p + blk);
            int4   b4 = __ldg(b4p + blk);
            float4 e4 = __ldg(e4p + blk);
            float tv[4] = {t4.x, t4.y, t4.z, t4.w};
            int   bv[4] = {b4.x, b4.y, b4.z, b4.w};
            float ev[4] = {e4.x, e4.y, e4.z, e4.w};
            #pragma unroll
            for (int e = 0; e < 4; ++e) {
                int gi = start + blk * 4 + e;
                mob_elem(r00, r01, r10, r11, tv[e], bv[e], ev[e], prev_t, gi,
                         sigma2, inv_sigma2, two_nie, a1, a2, a3);
            }
            if ((blk & 1) == 1) {   // renormalize every 8 elements
                float rn = fast_rcp(r11);
                r00 *= rn; r01 *= rn; r10 *= rn; r11 = 1.0f;
            }
        }
    } else {
        for (int i = start; i < end; ++i) {
            mob_elem(r00, r01, r10, r11, __ldg(t + i), __ldg(band + i),
                     __ldg(yerr + i), prev_t, i,
                     sigma2, inv_sigma2, two_nie, a1, a2, a3);
            float rn = fast_rcp(r11);
            r00 *= rn; r01 *= rn; r10 *= rn; r11 = 1.0f;
        }
    }
    float rn = fast_rcp(r11);
    g_segM[seg] = make_float4(r00 * rn, r01 * rn, r10 * rn, 1.0f);
}

// ------------------- Kernel 2: single-block scan over segment matrices ---------
__global__ void __launch_bounds__(SCAN_T) k2_scan(const float* __restrict__ lkp, int nseg)
{
    __shared__ float4 sm[SCAN_T];
    int j = threadIdx.x;
    float w0 = expf(-2.0f * lkp[0]);      // 1/sigma2 : initial w (cS0 = 0)
    int C = (nseg + SCAN_T - 1) / SCAN_T;
    int s0 = j * C;
    int s1 = min(s0 + C, nseg);

    float r00 = 1.f, r01 = 0.f, r10 = 0.f, r11 = 1.f;
    for (int k = s0; k < s1; ++k) {
        float4 m = g_segM[k];
        mob_compose_norm(r00, r01, r10, r11, m.x, m.y, m.z, m.w);
    }
    sm[j] = make_float4(r00, r01, r10, r11);
    __syncthreads();

    for (int d = 1; d < SCAN_T; d <<= 1) {
        float4 mine = sm[j];
        float4 oth  = make_float4(1.f, 0.f, 0.f, 1.f);
        bool h = (j >= d);
        if (h) oth = sm[j - d];
        __syncthreads();
        if (h) {
            float n00 = fmaf(mine.x, oth.x, mine.y * oth.z);
            float n01 = fmaf(mine.x, oth.y, mine.y * oth.w);
            float n10 = fmaf(mine.z, oth.x, mine.w * oth.z);
            float n11 = fmaf(mine.z, oth.y, mine.w * oth.w);
            float rn  = fast_rcp(n11);
            sm[j] = make_float4(n00 * rn, n01 * rn, n10 * rn, 1.0f);
        }
        __syncthreads();
    }

    float e00 = 1.f, e01 = 0.f, e10 = 0.f, e11 = 1.f;
    if (j > 0) { float4 E = sm[j - 1]; e00 = E.x; e01 = E.y; e10 = E.z; e11 = E.w; }
    for (int k = s0; k < s1; ++k) {
        g_win[k] = fmaf(e00, w0, e01) / fmaf(e10, w0, e11);
        float4 m = g_segM[k];
        mob_compose_norm(e00, e01, e10, e11, m.x, m.y, m.z, m.w);
    }
}

// ------------------- Kernel 3: exact in-segment recurrence ----------------------
__device__ __forceinline__ void k3_elem(
    float ti, int b, float ye, float yi, int gi, float& prev_t,
    float sigma2, float inv_sigma2, float nie, float two_nie,
    float a1, float a2, float a3,
    float& w, float& Ap, float& Bp,
    float& q0, float& qcd, float& q2, float& ld)
{
    float u  = pick_amp(b, a1, a2, a3);
    float U  = sigma2 * u;
    float UV = U * u;
    float e2 = ye * ye;
    float dt = ti - prev_t;
    prev_t = ti;
    float p    = (gi == 0) ? 0.0f : __expf(nie * dt);
    float omp2 = (gi == 0) ? 1.0f : -expm1f(two_nie * dt);   // 1 - p^2, accurate
    float p2   = 1.0f - omp2;

    float Dt   = fmaf(UV, omp2, e2);
    float U2p2 = U * U * p2;
    float D    = fmaf(U2p2, w, Dt);
    float invD = fast_rcp(D);
    float W    = fmaf(U * p2, w, u * omp2) * invD;   // (V(1-p2) + U p2 w)/D
    ld += __logf(D);

    float Up = U * p;
    float c  = fmaf(-Up, Bp, yi);                    // z = c - dd*cg_in
    float dd = Up * Ap;
    q0  = fmaf(c * invD, c, q0);
    qcd = fmaf(c * invD, dd, qcd);
    q2  = fmaf(dd * invD, dd, q2);

    float Astep = p * fmaf(-W, U, 1.0f);             // p(1 - W U)
    Bp = fmaf(Astep, Bp, W * yi);
    Ap = Astep * Ap;
    w  = e2 * fmaf(p2, w, inv_sigma2 * omp2) * invD; // w' >= 0
}

__global__ void __launch_bounds__(256) k3_seg(
    const float* __restrict__ t, const int* __restrict__ band,
    const float* __restrict__ y, const float* __restrict__ yerr,
    const float* __restrict__ lad, const float* __restrict__ lkp,
    int N, int nseg)
{
    int seg = blockIdx.x * blockDim.x + threadIdx.x;
    if (seg >= nseg) return;

    float sigma2 = expf(2.0f * lkp[0]);
    float inv_sigma2 = 1.0f / sigma2;
    float nie = -1.0f / expf(lkp[1]);
    float two_nie = 2.0f * nie;
    float a1 = expf(lad[0]), a2 = expf(lad[1]), a3 = expf(lad[2]);

    int start = seg * SEG_LEN;
    int end   = min(start + SEG_LEN, N);
    float prev_t = (start > 0) ? __ldg(t + start - 1) : 0.0f;

    float w  = g_win[seg];
    float Ap = 1.f, Bp = 0.f;
    float q0 = 0.f, qcd = 0.f, q2 = 0.f, ld = 0.f;

    if (end - start == SEG_LEN) {
        const float4* t4p = (const float4*)(t + start);
        const int4*   b4p = (const int4*)(band + start);
        const float4* y4p = (const float4*)(y + start);
        const float4* e4p = (const float4*)(yerr + start);
        #pragma unroll 1
        for (int blk = 0; blk < SEG_LEN / 4; ++blk) {
            float4 t4 = __ldg(t4p + blk);
            int4   b4 = __ldg(b4p + blk);
            float4 y4 = __ldg(y4p + blk);
            float4 e4 = __ldg(e4p + blk);
            float tv[4] = {t4.x, t4.y, t4.z, t4.w};
            int   bv[4] = {b4.x, b4.y, b4.z, b4.w};
            float yv[4] = {y4.x, y4.y, y4.z, y4.w};
            float ev[4] = {e4.x, e4.y, e4.z, e4.w};
            #pragma unroll
            for (int e = 0; e < 4; ++e) {
                int gi = start + blk * 4 + e;
                k3_elem(tv[e], bv[e], ev[e], yv[e], gi, prev_t,
                        sigma2, inv_sigma2, nie, two_nie, a1, a2, a3,
                        w, Ap, Bp, q0, qcd, q2, ld);
            }
        }
    } else {
        for (int i = start; i < end; ++i) {
            k3_elem(__ldg(t + i), __ldg(band + i), __ldg(yerr + i), __ldg(y + i),
                    i, prev_t, sigma2, inv_sigma2, nie, two_nie, a1, a2, a3,
                    w, Ap, Bp, q0, qcd, q2, ld);
        }
    }
    g_segA[seg] = make_float4(Ap, Bp, ld, 0.f);
    g_segQ[seg] = make_float4(q0, qcd, q2, 0.f);
}

// ------------------- Kernel 4: affine scan + final reduction --------------------
__global__ void __launch_bounds__(SCAN_T) k4_final(float* __restrict__ out, int N, int nseg)
{
    __shared__ float2 sm[SCAN_T];
    __shared__ double sred[SCAN_T];
    int j = threadIdx.x;
    int C = (nseg + SCAN_T - 1) / SCAN_T;
    int s0 = j * C;
    int s1 = min(s0 + C, nseg);

    float A = 1.f, B = 0.f;
    for (int k = s0; k < s1; ++k) {
        float4 v = g_segA[k];
        B = fmaf(v.x, B, v.y);
        A = v.x * A;
    }
    sm[j] = make_float2(A, B);
    __syncthreads();

    for (int d = 1; d < SCAN_T; d <<= 1) {
        float2 mine = sm[j];
        float2 oth  = make_float2(1.f, 0.f);
        bool h = (j >= d);
        if (h) oth = sm[j - d];
        __syncthreads();
        if (h) sm[j] = make_float2(mine.x * oth.x, fmaf(mine.x, oth.y, mine.y));
        __syncthreads();
    }

    float cg = (j > 0) ? sm[j - 1].y : 0.f;
    double acc = 0.0;
    for (int k = s0; k < s1; ++k) {
        float4 va = g_segA[k];
        float4 vq = g_segQ[k];
        float contrib = fmaf(vq.z * cg - 2.0f * vq.y, cg, vq.x) + va.z;
        acc += (double)contrib;
        cg = fmaf(va.x, cg, va.y);
    }
    sred[j] = acc;
    __syncthreads();
    for (int s = SCAN_T / 2; s > 0; s >>= 1) {
        if (j < s) sred[j] += sred[j + s];
        __syncthreads();
    }
    if (j == 0) {
        double total = sred[0] + (double)N * 1.837877066409345483560659472811; // log(2*pi)
        out[0] = (float)(-0.5 * total);
    }
}

extern "C" void kernel_launch(void* const* d_in, const int* in_sizes, int n_in,
                              void* d_out, int out_size)
{
    const float* t    = (const float*)d_in[0];
    const int*   band = (const int*)  d_in[1];
    const float* y    = (const float*)d_in[2];
    const float* yerr = (const float*)d_in[3];
    const float* lad  = (const float*)d_in[4];
    const float* lkp  = (const float*)d_in[5];
    float* out = (float*)d_out;

    int N = in_sizes[0];
    int nseg = (N + SEG_LEN - 1) / SEG_LEN;

    int threads = 256;
    int blocks  = (nseg + threads - 1) / threads;

    k1_mobius<<<blocks, threads>>>(t, band, yerr, lad, lkp, N, nseg);
    k2_scan<<<1, SCAN_T>>>(lkp, nseg);
    k3_seg<<<blocks, threads>>>(t, band, y, yerr, lad, lkp, N, nseg);
    k4_final<<<1, SCAN_T>>>(out, N, nseg);
}

// round 3
// speedup vs baseline: 3.5664x; 3.5664x over previous
#include <cuda_runtime.h>
#include <math.h>

// Celerite (single-term Exp kernel, multiband amplitudes) log-likelihood.
// Two-level grid-wide scans; no more monolithic single-block scan kernels.
//
//   kA: per-segment Mobius composition (w = 1/sigma2 - cS coords, all-positive
//       matrices) + in-block smem scan -> per-seg exclusive prefix + block composite
//   kB: tiny scan of block composites -> per-block exclusive Mobius prefix
//   kC: exact w_in per segment -> exact recurrence -> (A,B) affine + (Q0,Qcd,Q2)
//       + in-block affine scan + block-reduced sum(logD)
//   kD: tiny scan of block affine composites
//   kE: quad polynomial at exact cg per segment, block-reduced (double)
//   kF: deterministic final sum -> out
//
// w-step: w' = e2*( (1-p2)/sigma2 + p2*w ) / D,  D = Dt + U^2 p2 w,
//         Dt = e2 + U*u*(1-p2),  U = sigma2*u, e2 = yerr^2
// W = (u(1-p2) + U p2 w)/D ; cg' = p(1-WU) cg + W y ; z = y - U p cg_prev

#define SEG_LEN 32
#define TPB     256
#define MAX_SEG 131072
#define MAX_BLK 1024

__device__ float4 g_segPrefM[MAX_SEG];  // in-block exclusive Mobius prefix
__device__ float4 g_blockM[MAX_BLK];    // per-block Mobius composite
__device__ float4 g_blockPrefM[MAX_BLK];// across-block exclusive Mobius prefix
__device__ float2 g_segPrefA[MAX_SEG];  // in-block exclusive affine prefix
__device__ float4 g_segQ[MAX_SEG];      // {Q0, Qcd, Q2, 0}
__device__ float2 g_blockA[MAX_BLK];    // per-block affine composite
__device__ float2 g_blockPrefA[MAX_BLK];// across-block exclusive affine prefix
__device__ double g_partLd[MAX_BLK];
__device__ double g_partQ[MAX_BLK];

__device__ __forceinline__ float pick_amp(int b, float a1, float a2, float a3) {
    float u = 1.0f;
    u = (b == 1) ? a1 : u;
    u = (b == 2) ? a2 : u;
    u = (b == 3) ? a3 : u;
    return u;
}

__device__ __forceinline__ float fast_rcp(float x) { return __fdividef(1.0f, x); }

// n = later * earlier, normalized so n11 = 1 (all entries >= 0: no cancellation)
__device__ __forceinline__ float4 mob_mul_norm(float4 l, float4 e) {
    float n00 = fmaf(l.x, e.x, l.y * e.z);
    float n01 = fmaf(l.x, e.y, l.y * e.w);
    float n10 = fmaf(l.z, e.x, l.w * e.z);
    float n11 = fmaf(l.z, e.y, l.w * e.w);
    float rn  = fast_rcp(n11);
    return make_float4(n00 * rn, n01 * rn, n10 * rn, 1.0f);
}

// ------------------- kA: segment Mobius + in-block scan -------------------
__global__ void __launch_bounds__(TPB) kA_mobius(
    const float* __restrict__ t, const int* __restrict__ band,
    const float* __restrict__ yerr,
    const float* __restrict__ lad, const float* __restrict__ lkp,
    int N, int nseg)
{
    __shared__ float4 sm[TPB];
    int tid = threadIdx.x;
    int seg = blockIdx.x * TPB + tid;

    float sigma2 = expf(2.0f * lkp[0]);
    float inv_sigma2 = 1.0f / sigma2;
    float two_nie = -2.0f / expf(lkp[1]);
    float a1 = expf(lad[0]), a2 = expf(lad[1]), a3 = expf(lad[2]);

    float r00 = 1.f, r01 = 0.f, r10 = 0.f, r11 = 1.f;

    if (seg < nseg) {
        int start = seg * SEG_LEN;
        int end   = min(start + SEG_LEN, N);
        float prev_t = (start > 0) ? __ldg(t + start - 1) : 0.0f;

        if (end - start == SEG_LEN) {
            const float4* t4p = (const float4*)(t + start);
            const int4*   b4p = (const int4*)(band + start);
            const float4* e4p = (const float4*)(yerr + start);
            #pragma unroll 1
            for (int blk = 0; blk < SEG_LEN / 4; ++blk) {
                float4 t4 = __ldg(t4p + blk);
                int4   b4 = __ldg(b4p + blk);
                float4 e4 = __ldg(e4p + blk);
                float tv[4] = {t4.x, t4.y, t4.z, t4.w};
                int   bv[4] = {b4.x, b4.y, b4.z, b4.w};
                float ev[4] = {e4.x, e4.y, e4.z, e4.w};
                #pragma unroll
                for (int e = 0; e < 4; ++e) {
                    int gi = start + blk * 4 + e;
                    float u  = pick_amp(bv[e], a1, a2, a3);
                    float U  = sigma2 * u;
                    float UV = U * u;
                    float e2 = ev[e] * ev[e];
                    float omp2 = (gi == 0) ? 1.0f
                               : -expm1f(two_nie * (tv[e] - prev_t));
                    float p2 = 1.0f - omp2;
                    prev_t = tv[e];
                    float Dt    = fmaf(UV, omp2, e2);
                    float invDt = fast_rcp(Dt);
                    float m00 = p2 * e2 * invDt;
                    float m01 = inv_sigma2 * e2 * omp2 * invDt;
                    float m10 = U * U * p2 * invDt;
                    float n00 = fmaf(m00, r00, m01 * r10);
                    float n01 = fmaf(m00, r01, m01 * r11);
                    float n10 = fmaf(m10, r00, r10);
                    float n11 = fmaf(m10, r01, r11);
                    r00 = n00; r01 = n01; r10 = n10; r11 = n11;
                }
                if (blk & 1) {
                    float rn = fast_rcp(r11);
                    r00 *= rn; r01 *= rn; r10 *= rn; r11 = 1.0f;
                }
            }
        } else {
            for (int i = start; i < end; ++i) {
                float ti = __ldg(t + i);
                int   b  = __ldg(band + i);
                float ye = __ldg(yerr + i);
                float u  = pick_amp(b, a1, a2, a3);
                float U  = sigma2 * u;
                float e2 = ye * ye;
                float omp2 = (i == 0) ? 1.0f : -expm1f(two_nie * (ti - prev_t));
                float p2 = 1.0f - omp2;
                prev_t = ti;
                float Dt    = fmaf(U * u, omp2, e2);
                float invDt = fast_rcp(Dt);
                float m00 = p2 * e2 * invDt;
                float m01 = inv_sigma2 * e2 * omp2 * invDt;
                float m10 = U * U * p2 * invDt;
                float n00 = fmaf(m00, r00, m01 * r10);
                float n01 = fmaf(m00, r01, m01 * r11);
                float n10 = fmaf(m10, r00, r10);
                float n11 = fmaf(m10, r01, r11);
                float rn = fast_rcp(n11);
                r00 = n00 * rn; r01 = n01 * rn; r10 = n10 * rn; r11 = 1.0f;
            }
        }
        float rn = fast_rcp(r11);
        r00 *= rn; r01 *= rn; r10 *= rn; r11 = 1.0f;
    }

    sm[tid] = make_float4(r00, r01, r10, r11);
    __syncthreads();

    // Hillis-Steele inclusive scan (mine = later, sm[tid-d] = earlier)
    #pragma unroll
    for (int d = 1; d < TPB; d <<= 1) {
        float4 mine = sm[tid];
        float4 oth;
        bool h = (tid >= d);
        if (h) oth = sm[tid - d];
        __syncthreads();
        if (h) sm[tid] = mob_mul_norm(mine, oth);
        __syncthreads();
    }

    if (seg < nseg) {
        float4 excl = (tid == 0) ? make_float4(1.f, 0.f, 0.f, 1.f) : sm[tid - 1];
        g_segPrefM[seg] = excl;
    }
    if (tid == TPB - 1) g_blockM[blockIdx.x] = sm[tid];
}

// ------------------- kB: tiny scan of block Mobius composites ----------------
__global__ void __launch_bounds__(1024) kB_scan(int nblk)
{
    __shared__ float4 sm[1024];
    int j = threadIdx.x;
    float4 v = make_float4(1.f, 0.f, 0.f, 1.f);
    if (j < nblk) v = g_blockM[j];
    sm[j] = v;
    __syncthreads();
    #pragma unroll
    for (int d = 1; d < 1024; d <<= 1) {
        float4 mine = sm[j];
        float4 oth;
        bool h = (j >= d);
        if (h) oth = sm[j - d];
        __syncthreads();
        if (h) sm[j] = mob_mul_norm(mine, oth);
        __syncthreads();
    }
    if (j < nblk)
        g_blockPrefM[j] = (j == 0) ? make_float4(1.f, 0.f, 0.f, 1.f) : sm[j - 1];
}

// ------------------- kC: exact recurrence + in-block affine scan -------------
__global__ void __launch_bounds__(TPB) kC_seg(
    const float* __restrict__ t, const int* __restrict__ band,
    const float* __restrict__ y, const float* __restrict__ yerr,
    const float* __restrict__ lad, const float* __restrict__ lkp,
    int N, int nseg)
{
    __shared__ float2 sa[TPB];
    __shared__ double sd[TPB];
    int tid = threadIdx.x;
    int seg = blockIdx.x * TPB + tid;

    float sigma2 = expf(2.0f * lkp[0]);
    float inv_sigma2 = 1.0f / sigma2;
    float nie = -1.0f / expf(lkp[1]);
    float two_nie = 2.0f * nie;
    float a1 = expf(lad[0]), a2 = expf(lad[1]), a3 = expf(lad[2]);

    float Ap = 1.f, Bp = 0.f;
    float q0 = 0.f, qcd = 0.f, q2 = 0.f, ld = 0.f;

    if (seg < nseg) {
        // total prefix = inblock_excl (later) * block_excl (earlier)
        float4 mi = g_segPrefM[seg];
        float4 mb = g_blockPrefM[blockIdx.x];
        float4 tot = mob_mul_norm(mi, mb);
        float w0 = inv_sigma2;                       // cS0 = 0 -> w0 = 1/sigma2
        float w = fmaf(tot.x, w0, tot.y) / fmaf(tot.z, w0, tot.w);

        int start = seg * SEG_LEN;
        int end   = min(start + SEG_LEN, N);
        float prev_t = (start > 0) ? __ldg(t + start - 1) : 0.0f;

        if (end - start == SEG_LEN) {
            const float4* t4p = (const float4*)(t + start);
            const int4*   b4p = (const int4*)(band + start);
            const float4* y4p = (const float4*)(y + start);
            const float4* e4p = (const float4*)(yerr + start);
            #pragma unroll 1
            for (int blk = 0; blk < SEG_LEN / 4; ++blk) {
                float4 t4 = __ldg(t4p + blk);
                int4   b4 = __ldg(b4p + blk);
                float4 y4 = __ldg(y4p + blk);
                float4 e4 = __ldg(e4p + blk);
                float tv[4] = {t4.x, t4.y, t4.z, t4.w};
                int   bv[4] = {b4.x, b4.y, b4.z, b4.w};
                float yv[4] = {y4.x, y4.y, y4.z, y4.w};
                float ev[4] = {e4.x, e4.y, e4.z, e4.w};
                #pragma unroll
                for (int e = 0; e < 4; ++e) {
                    int gi = start + blk * 4 + e;
                    float u  = pick_amp(bv[e], a1, a2, a3);
                    float U  = sigma2 * u;
                    float e2 = ev[e] * ev[e];
                    float dt = tv[e] - prev_t;
                    prev_t = tv[e];
                    float p    = (gi == 0) ? 0.0f : __expf(nie * dt);
                    float omp2 = (gi == 0) ? 1.0f : -expm1f(two_nie * dt);
                    float p2   = 1.0f - omp2;
                    float Dt   = fmaf(U * u, omp2, e2);
                    float D    = fmaf(U * U * p2, w, Dt);
                    float invD = fast_rcp(D);
                    float W    = fmaf(U * p2, w, u * omp2) * invD;
                    ld += __logf(D);
                    float Up = U * p;
                    float c  = fmaf(-Up, Bp, yv[e]);
                    float dd = Up * Ap;
                    q0  = fmaf(c * invD, c, q0);
                    qcd = fmaf(c * invD, dd, qcd);
                    q2  = fmaf(dd * invD, dd, q2);
                    float Astep = p * fmaf(-W, U, 1.0f);
                    Bp = fmaf(Astep, Bp, W * yv[e]);
                    Ap = Astep * Ap;
                    w  = e2 * fmaf(p2, w, inv_sigma2 * omp2) * invD;
                }
            }
        } else {
            for (int i = start; i < end; ++i) {
                float ti = __ldg(t + i);
                int   b  = __ldg(band + i);
                float yi = __ldg(y + i);
                float ye = __ldg(yerr + i);
                float u  = pick_amp(b, a1, a2, a3);
                float U  = sigma2 * u;
                float e2 = ye * ye;
                float dt = ti - prev_t;
                prev_t = ti;
                float p    = (i == 0) ? 0.0f : __expf(nie * dt);
                float omp2 = (i == 0) ? 1.0f : -expm1f(two_nie * dt);
                float p2   = 1.0f - omp2;
                float Dt   = fmaf(U * u, omp2, e2);
                float D    = fmaf(U * U * p2, w, Dt);
                float invD = fast_rcp(D);
                float W    = fmaf(U * p2, w, u * omp2) * invD;
                ld += __logf(D);
                float Up = U * p;
                float c  = fmaf(-Up, Bp, yi);
                float dd = Up * Ap;
                q0  = fmaf(c * invD, c, q0);
                qcd = fmaf(c * invD, dd, qcd);
                q2  = fmaf(dd * invD, dd, q2);
                float Astep = p * fmaf(-W, U, 1.0f);
                Bp = fmaf(Astep, Bp, W * yi);
                Ap = Astep * Ap;
                w  = e2 * fmaf(p2, w, inv_sigma2 * omp2) * invD;
            }
        }
        g_segQ[seg] = make_float4(q0, qcd, q2, 0.f);
    }

    // in-block affine scan: (A_l,B_l) o (A_e,B_e) = (A_l A_e, A_l B_e + B_l)
    sa[tid] = make_float2(Ap, Bp);
    __syncthreads();
    #pragma unroll
    for (int d = 1; d < TPB; d <<= 1) {
        float2 mine = sa[tid];
        float2 oth;
        bool h = (tid >= d);
        if (h) oth = sa[tid - d];
        __syncthreads();
        if (h) sa[tid] = make_float2(mine.x * oth.x, fmaf(mine.x, oth.y, mine.y));
        __syncthreads();
    }
    if (seg < nseg)
        g_segPrefA[seg] = (tid == 0) ? make_float2(1.f, 0.f) : sa[tid - 1];
    if (tid == TPB - 1) g_blockA[blockIdx.x] = sa[tid];

    // block-reduce sum(logD) in double (fixed order -> deterministic)
    sd[tid] = (double)ld;
    __syncthreads();
    #pragma unroll
    for (int s = TPB / 2; s > 0; s >>= 1) {
        if (tid < s) sd[tid] += sd[tid + s];
        __syncthreads();
    }
    if (tid == 0) g_partLd[blockIdx.x] = sd[0];
}

// ------------------- kD: tiny scan of block affine composites ----------------
__global__ void __launch_bounds__(1024) kD_scan(int nblk)
{
    __shared__ float2 sm[1024];
    int j = threadIdx.x;
    float2 v = make_float2(1.f, 0.f);
    if (j < nblk) v = g_blockA[j];
    sm[j] = v;
    __syncthreads();
    #pragma unroll
    for (int d = 1; d < 1024; d <<= 1) {
        float2 mine = sm[j];
        float2 oth;
        bool h = (j >= d);
        if (h) oth = sm[j - d];
        __syncthreads();
        if (h) sm[j] = make_float2(mine.x * oth.x, fmaf(mine.x, oth.y, mine.y));
        __syncthreads();
    }
    if (j < nblk)
        g_blockPrefA[j] = (j == 0) ? make_float2(1.f, 0.f) : sm[j - 1];
}

// ------------------- kE: quad evaluation + block reduction -------------------
__global__ void __launch_bounds__(TPB) kE_quad(int nseg)
{
    __shared__ double sd[TPB];
    int tid = threadIdx.x;
    int seg = blockIdx.x * TPB + tid;

    float contrib = 0.f;
    if (seg < nseg) {
        float cgblk = g_blockPrefA[blockIdx.x].y;   // cg0 = 0
        float2 pr = g_segPrefA[seg];
        float cg = fmaf(pr.x, cgblk, pr.y);
        float4 q = g_segQ[seg];
        contrib = fmaf(q.z * cg - 2.0f * q.y, cg, q.x);
    }
    sd[tid] = (double)contrib;
    __syncthreads();
    #pragma unroll
    for (int s = TPB / 2; s > 0; s >>= 1) {
        if (tid < s) sd[tid] += sd[tid + s];
        __syncthreads();
    }
    if (tid == 0) g_partQ[blockIdx.x] = sd[0];
}

// ------------------- kF: deterministic final sum -----------------------------
__global__ void __launch_bounds__(1024) kF_final(float* __restrict__ out, int N, int nblk)
{
    __shared__ double sd[1024];
    int j = threadIdx.x;
    double v = 0.0;
    if (j < nblk) v = g_partLd[j] + g_partQ[j];
    sd[j] = v;
    __syncthreads();
    #pragma unroll
    for (int s = 512; s > 0; s >>= 1) {
        if (j < s) sd[j] += sd[j + s];
        __syncthreads();
    }
    if (j == 0) {
        double total = sd[0] + (double)N * 1.837877066409345483560659472811;
        out[0] = (float)(-0.5 * total);
    }
}

extern "C" void kernel_launch(void* const* d_in, const int* in_sizes, int n_in,
                              void* d_out, int out_size)
{
    const float* t    = (const float*)d_in[0];
    const int*   band = (const int*)  d_in[1];
    const float* y    = (const float*)d_in[2];
    const float* yerr = (const float*)d_in[3];
    const float* lad  = (const float*)d_in[4];
    const float* lkp  = (const float*)d_in[5];
    float* out = (float*)d_out;

    int N = in_sizes[0];
    int nseg = (N + SEG_LEN - 1) / SEG_LEN;
    int nblk = (nseg + TPB - 1) / TPB;

    kA_mobius<<<nblk, TPB>>>(t, band, yerr, lad, lkp, N, nseg);
    kB_scan<<<1, 1024>>>(nblk);
    kC_seg<<<nblk, TPB>>>(t, band, y, yerr, lad, lkp, N, nseg);
    kD_scan<<<1, 1024>>>(nblk);
    kE_quad<<<nblk, TPB>>>(nseg);
    kF_final<<<1, 1024>>>(out, N, nblk);
}

// round 4
// speedup vs baseline: 4.1866x; 1.1739x over previous
#include <cuda_runtime.h>
#include <math.h>

// Celerite (single-term Exp kernel, multiband amplitudes) log-likelihood.
// 3 launches:
//   kA: per-segment Mobius composition (w = 1/sigma2 - cS coords, all-positive
//       matrices) + in-block smem scan -> per-seg exclusive prefix + block composite
//   kC: per-block redundant scan of block composites -> exact w_in; exact
//       recurrence -> (A,B) affine + (Q0,Qcd,Q2); in-block affine scan;
//       block-reduced sum(logD)
//   kE: per-block redundant scan of block affine composites -> exact cg;
//       quad polynomial; block-reduce; last block does final deterministic sum.

#define SEG_LEN 32
#define TPB     256
#define MAX_SEG 131072
#define MAX_BLK 1024

__device__ float4 g_segPrefM[MAX_SEG];  // in-block exclusive Mobius prefix
__device__ float4 g_blockM[MAX_BLK];    // per-block Mobius composite
__device__ float2 g_segPrefA[MAX_SEG];  // in-block exclusive affine prefix
__device__ float4 g_segQ[MAX_SEG];      // {Q0, Qcd, Q2, 0}
__device__ float2 g_blockA[MAX_BLK];    // per-block affine composite
__device__ double g_partLd[MAX_BLK];
__device__ double g_partQ[MAX_BLK];
__device__ int    g_done = 0;           // self-resetting ticket

__device__ __forceinline__ float pick_amp(int b, float a1, float a2, float a3) {
    float u = 1.0f;
    u = (b == 1) ? a1 : u;
    u = (b == 2) ? a2 : u;
    u = (b == 3) ? a3 : u;
    return u;
}

__device__ __forceinline__ float fast_rcp(float x) { return __fdividef(1.0f, x); }

// n = later * earlier, normalized so n11 = 1 (all entries >= 0: no cancellation)
__device__ __forceinline__ float4 mob_mul_norm(float4 l, float4 e) {
    float n00 = fmaf(l.x, e.x, l.y * e.z);
    float n01 = fmaf(l.x, e.y, l.y * e.w);
    float n10 = fmaf(l.z, e.x, l.w * e.z);
    float n11 = fmaf(l.z, e.y, l.w * e.w);
    float rn  = fast_rcp(n11);
    return make_float4(n00 * rn, n01 * rn, n10 * rn, 1.0f);
}

// ------------------- kA: segment Mobius + in-block scan -------------------
__global__ void __launch_bounds__(TPB) kA_mobius(
    const float* __restrict__ t, const int* __restrict__ band,
    const float* __restrict__ yerr,
    const float* __restrict__ lad, const float* __restrict__ lkp,
    int N, int nseg)
{
    __shared__ float4 sm[TPB];
    int tid = threadIdx.x;
    int seg = blockIdx.x * TPB + tid;

    float sigma2 = expf(2.0f * lkp[0]);
    float inv_sigma2 = 1.0f / sigma2;
    float two_nie = -2.0f / expf(lkp[1]);
    float a1 = expf(lad[0]), a2 = expf(lad[1]), a3 = expf(lad[2]);

    float r00 = 1.f, r01 = 0.f, r10 = 0.f, r11 = 1.f;

    if (seg < nseg) {
        int start = seg * SEG_LEN;
        int end   = min(start + SEG_LEN, N);
        float prev_t = (start > 0) ? __ldg(t + start - 1) : 0.0f;

        if (end - start == SEG_LEN) {
            const float4* t4p = (const float4*)(t + start);
            const int4*   b4p = (const int4*)(band + start);
            const float4* e4p = (const float4*)(yerr + start);
            #pragma unroll 1
            for (int blk = 0; blk < SEG_LEN / 4; ++blk) {
                float4 t4 = __ldg(t4p + blk);
                int4   b4 = __ldg(b4p + blk);
                float4 e4 = __ldg(e4p + blk);
                float tv[4] = {t4.x, t4.y, t4.z, t4.w};
                int   bv[4] = {b4.x, b4.y, b4.z, b4.w};
                float ev[4] = {e4.x, e4.y, e4.z, e4.w};
                #pragma unroll
                for (int e = 0; e < 4; ++e) {
                    int gi = start + blk * 4 + e;
                    float u  = pick_amp(bv[e], a1, a2, a3);
                    float U  = sigma2 * u;
                    float e2 = ev[e] * ev[e];
                    float omp2 = (gi == 0) ? 1.0f
                               : -expm1f(two_nie * (tv[e] - prev_t));
                    float p2 = 1.0f - omp2;
                    prev_t = tv[e];
                    float Dt    = fmaf(U * u, omp2, e2);
                    float invDt = fast_rcp(Dt);
                    float m00 = p2 * e2 * invDt;
                    float m01 = inv_sigma2 * e2 * omp2 * invDt;
                    float m10 = U * U * p2 * invDt;
                    float n00 = fmaf(m00, r00, m01 * r10);
                    float n01 = fmaf(m00, r01, m01 * r11);
                    float n10 = fmaf(m10, r00, r10);
                    float n11 = fmaf(m10, r01, r11);
                    r00 = n00; r01 = n01; r10 = n10; r11 = n11;
                }
                if (blk & 1) {
                    float rn = fast_rcp(r11);
                    r00 *= rn; r01 *= rn; r10 *= rn; r11 = 1.0f;
                }
            }
        } else {
            for (int i = start; i < end; ++i) {
                float ti = __ldg(t + i);
                int   b  = __ldg(band + i);
                float ye = __ldg(yerr + i);
                float u  = pick_amp(b, a1, a2, a3);
                float U  = sigma2 * u;
                float e2 = ye * ye;
                float omp2 = (i == 0) ? 1.0f : -expm1f(two_nie * (ti - prev_t));
                float p2 = 1.0f - omp2;
                prev_t = ti;
                float Dt    = fmaf(U * u, omp2, e2);
                float invDt = fast_rcp(Dt);
                float m00 = p2 * e2 * invDt;
                float m01 = inv_sigma2 * e2 * omp2 * invDt;
                float m10 = U * U * p2 * invDt;
                float n00 = fmaf(m00, r00, m01 * r10);
                float n01 = fmaf(m00, r01, m01 * r11);
                float n10 = fmaf(m10, r00, r10);
                float n11 = fmaf(m10, r01, r11);
                float rn = fast_rcp(n11);
                r00 = n00 * rn; r01 = n01 * rn; r10 = n10 * rn; r11 = 1.0f;
            }
        }
        float rn = fast_rcp(r11);
        r00 *= rn; r01 *= rn; r10 *= rn; r11 = 1.0f;
    }

    sm[tid] = make_float4(r00, r01, r10, r11);
    __syncthreads();

    #pragma unroll
    for (int d = 1; d < TPB; d <<= 1) {
        float4 mine = sm[tid];
        float4 oth;
        bool h = (tid >= d);
        if (h) oth = sm[tid - d];
        __syncthreads();
        if (h) sm[tid] = mob_mul_norm(mine, oth);
        __syncthreads();
    }

    if (seg < nseg) {
        float4 excl = (tid == 0) ? make_float4(1.f, 0.f, 0.f, 1.f) : sm[tid - 1];
        g_segPrefM[seg] = excl;
    }
    if (tid == TPB - 1) g_blockM[blockIdx.x] = sm[tid];
}

// ------------------- kC: block-prefix recompute + exact recurrence -----------
__global__ void __launch_bounds__(TPB) kC_seg(
    const float* __restrict__ t, const int* __restrict__ band,
    const float* __restrict__ y, const float* __restrict__ yerr,
    const float* __restrict__ lad, const float* __restrict__ lkp,
    int N, int nseg, int nblk)
{
    __shared__ float4 sm4[TPB];
    __shared__ float2 sa[TPB];
    __shared__ double sd[TPB];
    int tid = threadIdx.x;
    int seg = blockIdx.x * TPB + tid;

    // --- redundant scan of block Mobius composites: this block's excl prefix ---
    int C = (nblk + TPB - 1) / TPB;
    {
        float4 r = make_float4(1.f, 0.f, 0.f, 1.f);
        int s0 = tid * C, s1 = min(s0 + C, nblk);
        for (int k = s0; k < s1; ++k) r = mob_mul_norm(g_blockM[k], r);
        sm4[tid] = r;
        __syncthreads();
        #pragma unroll
        for (int d = 1; d < TPB; d <<= 1) {
            float4 mine = sm4[tid];
            float4 oth;
            bool h = (tid >= d);
            if (h) oth = sm4[tid - d];
            __syncthreads();
            if (h) sm4[tid] = mob_mul_norm(mine, oth);
            __syncthreads();
        }
    }
    // exclusive prefix for block blockIdx.x (generic C>1 path refines below)
    float4 mb = make_float4(1.f, 0.f, 0.f, 1.f);
    {
        int bq = blockIdx.x / C;     // which chunk holds our block
        int br = blockIdx.x % C;
        if (bq > 0) mb = sm4[bq - 1];
        int s0 = bq * C;
        for (int k = s0; k < s0 + br; ++k) mb = mob_mul_norm(g_blockM[k], mb);
    }
    __syncthreads();

    float sigma2 = expf(2.0f * lkp[0]);
    float inv_sigma2 = 1.0f / sigma2;
    float nie = -1.0f / expf(lkp[1]);
    float two_nie = 2.0f * nie;
    float a1 = expf(lad[0]), a2 = expf(lad[1]), a3 = expf(lad[2]);

    float Ap = 1.f, Bp = 0.f;
    float q0 = 0.f, qcd = 0.f, q2 = 0.f, ld = 0.f;

    if (seg < nseg) {
        float4 mi = g_segPrefM[seg];
        float4 tot = mob_mul_norm(mi, mb);
        float w0 = inv_sigma2;                       // cS0 = 0 -> w0 = 1/sigma2
        float w = fmaf(tot.x, w0, tot.y) / fmaf(tot.z, w0, tot.w);

        int start = seg * SEG_LEN;
        int end   = min(start + SEG_LEN, N);
        float prev_t = (start > 0) ? __ldg(t + start - 1) : 0.0f;

        if (end - start == SEG_LEN) {
            const float4* t4p = (const float4*)(t + start);
            const int4*   b4p = (const int4*)(band + start);
            const float4* y4p = (const float4*)(y + start);
            const float4* e4p = (const float4*)(yerr + start);
            #pragma unroll 1
            for (int blk = 0; blk < SEG_LEN / 4; ++blk) {
                float4 t4 = __ldg(t4p + blk);
                int4   b4 = __ldg(b4p + blk);
                float4 y4 = __ldg(y4p + blk);
                float4 e4 = __ldg(e4p + blk);
                float tv[4] = {t4.x, t4.y, t4.z, t4.w};
                int   bv[4] = {b4.x, b4.y, b4.z, b4.w};
                float yv[4] = {y4.x, y4.y, y4.z, y4.w};
                float ev[4] = {e4.x, e4.y, e4.z, e4.w};
                #pragma unroll
                for (int e = 0; e < 4; ++e) {
                    int gi = start + blk * 4 + e;
                    float u  = pick_amp(bv[e], a1, a2, a3);
                    float U  = sigma2 * u;
                    float e2 = ev[e] * ev[e];
                    float dt = tv[e] - prev_t;
                    prev_t = tv[e];
                    float p    = (gi == 0) ? 0.0f : __expf(nie * dt);
                    float omp2 = (gi == 0) ? 1.0f : -expm1f(two_nie * dt);
                    float p2   = 1.0f - omp2;
                    float Dt   = fmaf(U * u, omp2, e2);
                    float D    = fmaf(U * U * p2, w, Dt);
                    float invD = fast_rcp(D);
                    float W    = fmaf(U * p2, w, u * omp2) * invD;
                    ld += __logf(D);
                    float Up = U * p;
                    float c  = fmaf(-Up, Bp, yv[e]);
                    float dd = Up * Ap;
                    q0  = fmaf(c * invD, c, q0);
                    qcd = fmaf(c * invD, dd, qcd);
                    q2  = fmaf(dd * invD, dd, q2);
                    float Astep = p * fmaf(-W, U, 1.0f);
                    Bp = fmaf(Astep, Bp, W * yv[e]);
                    Ap = Astep * Ap;
                    w  = e2 * fmaf(p2, w, inv_sigma2 * omp2) * invD;
                }
            }
        } else {
            for (int i = start; i < end; ++i) {
                float ti = __ldg(t + i);
                int   b  = __ldg(band + i);
                float yi = __ldg(y + i);
                float ye = __ldg(yerr + i);
                float u  = pick_amp(b, a1, a2, a3);
                float U  = sigma2 * u;
                float e2 = ye * ye;
                float dt = ti - prev_t;
                prev_t = ti;
                float p    = (i == 0) ? 0.0f : __expf(nie * dt);
                float omp2 = (i == 0) ? 1.0f : -expm1f(two_nie * dt);
                float p2   = 1.0f - omp2;
                float Dt   = fmaf(U * u, omp2, e2);
                float D    = fmaf(U * U * p2, w, Dt);
                float invD = fast_rcp(D);
                float W    = fmaf(U * p2, w, u * omp2) * invD;
                ld += __logf(D);
                float Up = U * p;
                float c  = fmaf(-Up, Bp, yi);
                float dd = Up * Ap;
                q0  = fmaf(c * invD, c, q0);
                qcd = fmaf(c * invD, dd, qcd);
                q2  = fmaf(dd * invD, dd, q2);
                float Astep = p * fmaf(-W, U, 1.0f);
                Bp = fmaf(Astep, Bp, W * yi);
                Ap = Astep * Ap;
                w  = e2 * fmaf(p2, w, inv_sigma2 * omp2) * invD;
            }
        }
        g_segQ[seg] = make_float4(q0, qcd, q2, 0.f);
    }

    // in-block affine scan: (A_l,B_l) o (A_e,B_e) = (A_l A_e, A_l B_e + B_l)
    sa[tid] = make_float2(Ap, Bp);
    __syncthreads();
    #pragma unroll
    for (int d = 1; d < TPB; d <<= 1) {
        float2 mine = sa[tid];
        float2 oth;
        bool h = (tid >= d);
        if (h) oth = sa[tid - d];
        __syncthreads();
        if (h) sa[tid] = make_float2(mine.x * oth.x, fmaf(mine.x, oth.y, mine.y));
        __syncthreads();
    }
    if (seg < nseg)
        g_segPrefA[seg] = (tid == 0) ? make_float2(1.f, 0.f) : sa[tid - 1];
    if (tid == TPB - 1) g_blockA[blockIdx.x] = sa[tid];

    sd[tid] = (double)ld;
    __syncthreads();
    #pragma unroll
    for (int s = TPB / 2; s > 0; s >>= 1) {
        if (tid < s) sd[tid] += sd[tid + s];
        __syncthreads();
    }
    if (tid == 0) g_partLd[blockIdx.x] = sd[0];
}

// ------------------- kE: affine block-prefix recompute + quad + final --------
__global__ void __launch_bounds__(TPB) kE_quad(float* __restrict__ out, int N, int nseg, int nblk)
{
    __shared__ float2 sa[TPB];
    __shared__ double sd[TPB];
    __shared__ bool s_last;
    int tid = threadIdx.x;
    int seg = blockIdx.x * TPB + tid;

    // --- redundant scan of block affine composites ---
    int C = (nblk + TPB - 1) / TPB;
    {
        float2 r = make_float2(1.f, 0.f);
        int s0 = tid * C, s1 = min(s0 + C, nblk);
        for (int k = s0; k < s1; ++k) {
            float2 v = g_blockA[k];
            r = make_float2(v.x * r.x, fmaf(v.x, r.y, v.y));
        }
        sa[tid] = r;
        __syncthreads();
        #pragma unroll
        for (int d = 1; d < TPB; d <<= 1) {
            float2 mine = sa[tid];
            float2 oth;
            bool h = (tid >= d);
            if (h) oth = sa[tid - d];
            __syncthreads();
            if (h) sa[tid] = make_float2(mine.x * oth.x, fmaf(mine.x, oth.y, mine.y));
            __syncthreads();
        }
    }
    float cgblk = 0.f;   // cg entering this block (cg0 = 0)
    {
        int bq = blockIdx.x / C;
        int br = blockIdx.x % C;
        float2 mb = make_float2(1.f, 0.f);
        if (bq > 0) mb = sa[bq - 1];
        int s0 = bq * C;
        for (int k = s0; k < s0 + br; ++k) {
            float2 v = g_blockA[k];
            mb = make_float2(v.x * mb.x, fmaf(v.x, mb.y, v.y));
        }
        cgblk = mb.y;
    }
    __syncthreads();

    float contrib = 0.f;
    if (seg < nseg) {
        float2 pr = g_segPrefA[seg];
        float cg = fmaf(pr.x, cgblk, pr.y);
        float4 q = g_segQ[seg];
        contrib = fmaf(q.z * cg - 2.0f * q.y, cg, q.x);
    }
    sd[tid] = (double)contrib;
    __syncthreads();
    #pragma unroll
    for (int s = TPB / 2; s > 0; s >>= 1) {
        if (tid < s) sd[tid] += sd[tid + s];
        __syncthreads();
    }
    if (tid == 0) {
        g_partQ[blockIdx.x] = sd[0];
        __threadfence();
        int prev = atomicAdd(&g_done, 1);
        s_last = (prev == gridDim.x - 1);
    }
    __syncthreads();

    if (s_last) {
        // final deterministic reduction over nblk partials
        double acc = 0.0;
        for (int k = tid; k < nblk; k += TPB) acc += g_partLd[k] + g_partQ[k];
        sd[tid] = acc;
        __syncthreads();
        #pragma unroll
        for (int s = TPB / 2; s > 0; s >>= 1) {
            if (tid < s) sd[tid] += sd[tid + s];
            __syncthreads();
        }
        if (tid == 0) {
            double total = sd[0] + (double)N * 1.837877066409345483560659472811;
            out[0] = (float)(-0.5 * total);
            atomicExch(&g_done, 0);   // self-reset for graph replay
        }
    }
}

extern "C" void kernel_launch(void* const* d_in, const int* in_sizes, int n_in,
                              void* d_out, int out_size)
{
    const float* t    = (const float*)d_in[0];
    const int*   band = (const int*)  d_in[1];
    const float* y    = (const float*)d_in[2];
    const float* yerr = (const float*)d_in[3];
    const float* lad  = (const float*)d_in[4];
    const float* lkp  = (const float*)d_in[5];
    float* out = (float*)d_out;

    int N = in_sizes[0];
    int nseg = (N + SEG_LEN - 1) / SEG_LEN;
    int nblk = (nseg + TPB - 1) / TPB;

    kA_mobius<<<nblk, TPB>>>(t, band, yerr, lad, lkp, N, nseg);
    kC_seg<<<nblk, TPB>>>(t, band, y, yerr, lad, lkp, N, nseg, nblk);
    kE_quad<<<nblk, TPB>>>(out, N, nseg, nblk);
}

// round 5
// speedup vs baseline: 4.4103x; 1.0534x over previous
#include <cuda_runtime.h>
#include <math.h>

// Celerite (single-term Exp kernel, multiband amplitudes) log-likelihood.
// 3 launches, SEG_LEN=16, warp-shuffle block scans:
//   kA: per-segment Mobius composition (w = 1/sigma2 - cS coords, all-positive
//       matrices) + in-block scan -> per-seg exclusive prefix + block composite
//   kC: per-block redundant scan of block composites -> exact w_in; exact
//       recurrence -> (A,B) affine + (Q0,Qcd,Q2); in-block affine scan;
//       block-reduced sum(logD)
//   kE: per-block redundant scan of block affine composites -> exact cg;
//       quad polynomial; block-reduce; last block does final deterministic sum.

#define SEG_LEN 16
#define TPB     256
#define NWARP   (TPB / 32)
#define MAX_SEG 131072
#define MAX_BLK 1024

__device__ float4 g_segPrefM[MAX_SEG];  // in-block exclusive Mobius prefix
__device__ float4 g_blockM[MAX_BLK];    // per-block Mobius composite
__device__ float2 g_segPrefA[MAX_SEG];  // in-block exclusive affine prefix
__device__ float4 g_segQ[MAX_SEG];      // {Q0, Qcd, Q2, 0}
__device__ float2 g_blockA[MAX_BLK];    // per-block affine composite
__device__ double g_partLd[MAX_BLK];
__device__ double g_partQ[MAX_BLK];
__device__ int    g_done = 0;           // self-resetting ticket

__device__ __forceinline__ float pick_amp(int b, float a1, float a2, float a3) {
    float u = 1.0f;
    u = (b == 1) ? a1 : u;
    u = (b == 2) ? a2 : u;
    u = (b == 3) ? a3 : u;
    return u;
}

__device__ __forceinline__ float fast_rcp(float x) { return __fdividef(1.0f, x); }

// n = later * earlier, normalized so n11 = 1 (all entries >= 0: no cancellation)
__device__ __forceinline__ float4 mob_mul_norm(float4 l, float4 e) {
    float n00 = fmaf(l.x, e.x, l.y * e.z);
    float n01 = fmaf(l.x, e.y, l.y * e.w);
    float n10 = fmaf(l.z, e.x, l.w * e.z);
    float n11 = fmaf(l.z, e.y, l.w * e.w);
    float rn  = fast_rcp(n11);
    return make_float4(n00 * rn, n01 * rn, n10 * rn, 1.0f);
}

__device__ __forceinline__ float2 aff_mul(float2 l, float2 e) {
    return make_float2(l.x * e.x, fmaf(l.x, e.y, l.y));
}

// Block-wide INCLUSIVE Mobius scan via warp shuffles.
// Writes inclusive results into sm[tid]; returns after a final __syncthreads(),
// so all of sm[] is readable.
__device__ __forceinline__ void block_scan_mob(float4 v, float4* sm, float4* wb, int tid)
{
    int lane = tid & 31, wid = tid >> 5;
    #pragma unroll
    for (int d = 1; d < 32; d <<= 1) {
        float4 o;
        o.x = __shfl_up_sync(0xffffffffu, v.x, d);
        o.y = __shfl_up_sync(0xffffffffu, v.y, d);
        o.z = __shfl_up_sync(0xffffffffu, v.z, d);
        o.w = __shfl_up_sync(0xffffffffu, v.w, d);
        if (lane >= d) v = mob_mul_norm(v, o);
    }
    if (lane == 31) wb[wid] = v;
    __syncthreads();
    if (wid == 0) {
        float4 wv = (lane < NWARP) ? wb[lane] : make_float4(1.f, 0.f, 0.f, 1.f);
        #pragma unroll
        for (int d = 1; d < NWARP; d <<= 1) {
            float4 o;
            o.x = __shfl_up_sync(0xffffffffu, wv.x, d);
            o.y = __shfl_up_sync(0xffffffffu, wv.y, d);
            o.z = __shfl_up_sync(0xffffffffu, wv.z, d);
            o.w = __shfl_up_sync(0xffffffffu, wv.w, d);
            if (lane >= d) wv = mob_mul_norm(wv, o);
        }
        if (lane < NWARP) wb[lane] = wv;
    }
    __syncthreads();
    if (wid > 0) v = mob_mul_norm(v, wb[wid - 1]);
    sm[tid] = v;
    __syncthreads();
}

// Block-wide INCLUSIVE affine scan via warp shuffles (same contract).
__device__ __forceinline__ void block_scan_aff(float2 v, float2* sm, float2* wb, int tid)
{
    int lane = tid & 31, wid = tid >> 5;
    #pragma unroll
    for (int d = 1; d < 32; d <<= 1) {
        float2 o;
        o.x = __shfl_up_sync(0xffffffffu, v.x, d);
        o.y = __shfl_up_sync(0xffffffffu, v.y, d);
        if (lane >= d) v = aff_mul(v, o);
    }
    if (lane == 31) wb[wid] = v;
    __syncthreads();
    if (wid == 0) {
        float2 wv = (lane < NWARP) ? wb[lane] : make_float2(1.f, 0.f);
        #pragma unroll
        for (int d = 1; d < NWARP; d <<= 1) {
            float2 o;
            o.x = __shfl_up_sync(0xffffffffu, wv.x, d);
            o.y = __shfl_up_sync(0xffffffffu, wv.y, d);
            if (lane >= d) wv = aff_mul(wv, o);
        }
        if (lane < NWARP) wb[lane] = wv;
    }
    __syncthreads();
    if (wid > 0) v = aff_mul(v, wb[wid - 1]);
    sm[tid] = v;
    __syncthreads();
}

// ------------------- kA: segment Mobius + in-block scan -------------------
__global__ void __launch_bounds__(TPB) kA_mobius(
    const float* __restrict__ t, const int* __restrict__ band,
    const float* __restrict__ yerr,
    const float* __restrict__ lad, const float* __restrict__ lkp,
    int N, int nseg)
{
    __shared__ float4 sm[TPB];
    __shared__ float4 wb[NWARP];
    int tid = threadIdx.x;
    int seg = blockIdx.x * TPB + tid;

    float sigma2 = expf(2.0f * lkp[0]);
    float inv_sigma2 = 1.0f / sigma2;
    float two_nie = -2.0f / expf(lkp[1]);
    float a1 = expf(lad[0]), a2 = expf(lad[1]), a3 = expf(lad[2]);

    float r00 = 1.f, r01 = 0.f, r10 = 0.f, r11 = 1.f;

    if (seg < nseg) {
        int start = seg * SEG_LEN;
        int end   = min(start + SEG_LEN, N);
        float prev_t = (start > 0) ? __ldg(t + start - 1) : 0.0f;

        if (end - start == SEG_LEN) {
            const float4* t4p = (const float4*)(t + start);
            const int4*   b4p = (const int4*)(band + start);
            const float4* e4p = (const float4*)(yerr + start);
            #pragma unroll 1
            for (int blk = 0; blk < SEG_LEN / 4; ++blk) {
                float4 t4 = __ldg(t4p + blk);
                int4   b4 = __ldg(b4p + blk);
                float4 e4 = __ldg(e4p + blk);
                float tv[4] = {t4.x, t4.y, t4.z, t4.w};
                int   bv[4] = {b4.x, b4.y, b4.z, b4.w};
                float ev[4] = {e4.x, e4.y, e4.z, e4.w};
                #pragma unroll
                for (int e = 0; e < 4; ++e) {
                    int gi = start + blk * 4 + e;
                    float u  = pick_amp(bv[e], a1, a2, a3);
                    float U  = sigma2 * u;
                    float e2 = ev[e] * ev[e];
                    float omp2 = (gi == 0) ? 1.0f
                               : -expm1f(two_nie * (tv[e] - prev_t));
                    float p2 = 1.0f - omp2;
                    prev_t = tv[e];
                    float Dt    = fmaf(U * u, omp2, e2);
                    float invDt = fast_rcp(Dt);
                    float m00 = p2 * e2 * invDt;
                    float m01 = inv_sigma2 * e2 * omp2 * invDt;
                    float m10 = U * U * p2 * invDt;
                    float n00 = fmaf(m00, r00, m01 * r10);
                    float n01 = fmaf(m00, r01, m01 * r11);
                    float n10 = fmaf(m10, r00, r10);
                    float n11 = fmaf(m10, r01, r11);
                    r00 = n00; r01 = n01; r10 = n10; r11 = n11;
                }
                if (blk & 1) {
                    float rn = fast_rcp(r11);
                    r00 *= rn; r01 *= rn; r10 *= rn; r11 = 1.0f;
                }
            }
        } else {
            for (int i = start; i < end; ++i) {
                float ti = __ldg(t + i);
                int   b  = __ldg(band + i);
                float ye = __ldg(yerr + i);
                float u  = pick_amp(b, a1, a2, a3);
                float U  = sigma2 * u;
                float e2 = ye * ye;
                float omp2 = (i == 0) ? 1.0f : -expm1f(two_nie * (ti - prev_t));
                float p2 = 1.0f - omp2;
                prev_t = ti;
                float Dt    = fmaf(U * u, omp2, e2);
                float invDt = fast_rcp(Dt);
                float m00 = p2 * e2 * invDt;
                float m01 = inv_sigma2 * e2 * omp2 * invDt;
                float m10 = U * U * p2 * invDt;
                float n00 = fmaf(m00, r00, m01 * r10);
                float n01 = fmaf(m00, r01, m01 * r11);
                float n10 = fmaf(m10, r00, r10);
                float n11 = fmaf(m10, r01, r11);
                float rn = fast_rcp(n11);
                r00 = n00 * rn; r01 = n01 * rn; r10 = n10 * rn; r11 = 1.0f;
            }
        }
        float rn = fast_rcp(r11);
        r00 *= rn; r01 *= rn; r10 *= rn; r11 = 1.0f;
    }

    block_scan_mob(make_float4(r00, r01, r10, r11), sm, wb, tid);

    if (seg < nseg) {
        float4 excl = (tid == 0) ? make_float4(1.f, 0.f, 0.f, 1.f) : sm[tid - 1];
        g_segPrefM[seg] = excl;
    }
    if (tid == TPB - 1) g_blockM[blockIdx.x] = sm[tid];
}

// ------------------- kC: block-prefix recompute + exact recurrence -----------
__global__ void __launch_bounds__(TPB) kC_seg(
    const float* __restrict__ t, const int* __restrict__ band,
    const float* __restrict__ y, const float* __restrict__ yerr,
    const float* __restrict__ lad, const float* __restrict__ lkp,
    int N, int nseg, int nblk)
{
    __shared__ float4 sm4[TPB];
    __shared__ float4 wb4[NWARP];
    __shared__ float2 sa[TPB];
    __shared__ float2 wb2[NWARP];
    __shared__ double sd[TPB];
    int tid = threadIdx.x;
    int seg = blockIdx.x * TPB + tid;

    // --- redundant scan of block Mobius composites: this block's excl prefix ---
    int C = (nblk + TPB - 1) / TPB;
    {
        float4 r = make_float4(1.f, 0.f, 0.f, 1.f);
        int s0 = tid * C, s1 = min(s0 + C, nblk);
        for (int k = s0; k < s1; ++k) r = mob_mul_norm(g_blockM[k], r);
        block_scan_mob(r, sm4, wb4, tid);
    }
    float4 mb = make_float4(1.f, 0.f, 0.f, 1.f);
    {
        int bq = blockIdx.x / C;
        int br = blockIdx.x % C;
        if (bq > 0) mb = sm4[bq - 1];
        int s0 = bq * C;
        for (int k = s0; k < s0 + br; ++k) mb = mob_mul_norm(g_blockM[k], mb);
    }
    __syncthreads();

    float sigma2 = expf(2.0f * lkp[0]);
    float inv_sigma2 = 1.0f / sigma2;
    float nie = -1.0f / expf(lkp[1]);
    float two_nie = 2.0f * nie;
    float a1 = expf(lad[0]), a2 = expf(lad[1]), a3 = expf(lad[2]);

    float Ap = 1.f, Bp = 0.f;
    float q0 = 0.f, qcd = 0.f, q2 = 0.f, ld = 0.f;

    if (seg < nseg) {
        float4 mi = g_segPrefM[seg];
        float4 tot = mob_mul_norm(mi, mb);
        float w0 = inv_sigma2;                       // cS0 = 0 -> w0 = 1/sigma2
        float w = fmaf(tot.x, w0, tot.y) / fmaf(tot.z, w0, tot.w);

        int start = seg * SEG_LEN;
        int end   = min(start + SEG_LEN, N);
        float prev_t = (start > 0) ? __ldg(t + start - 1) : 0.0f;

        if (end - start == SEG_LEN) {
            const float4* t4p = (const float4*)(t + start);
            const int4*   b4p = (const int4*)(band + start);
            const float4* y4p = (const float4*)(y + start);
            const float4* e4p = (const float4*)(yerr + start);
            #pragma unroll 1
            for (int blk = 0; blk < SEG_LEN / 4; ++blk) {
                float4 t4 = __ldg(t4p + blk);
                int4   b4 = __ldg(b4p + blk);
                float4 y4 = __ldg(y4p + blk);
                float4 e4 = __ldg(e4p + blk);
                float tv[4] = {t4.x, t4.y, t4.z, t4.w};
                int   bv[4] = {b4.x, b4.y, b4.z, b4.w};
                float yv[4] = {y4.x, y4.y, y4.z, y4.w};
                float ev[4] = {e4.x, e4.y, e4.z, e4.w};
                #pragma unroll
                for (int e = 0; e < 4; ++e) {
                    int gi = start + blk * 4 + e;
                    float u  = pick_amp(bv[e], a1, a2, a3);
                    float U  = sigma2 * u;
                    float e2 = ev[e] * ev[e];
                    float dt = tv[e] - prev_t;
                    prev_t = tv[e];
                    float p    = (gi == 0) ? 0.0f : __expf(nie * dt);
                    float omp2 = (gi == 0) ? 1.0f : -expm1f(two_nie * dt);
                    float p2   = 1.0f - omp2;
                    float Dt   = fmaf(U * u, omp2, e2);
                    float D    = fmaf(U * U * p2, w, Dt);
                    float invD = fast_rcp(D);
                    float W    = fmaf(U * p2, w, u * omp2) * invD;
                    ld += __logf(D);
                    float Up = U * p;
                    float c  = fmaf(-Up, Bp, yv[e]);
                    float dd = Up * Ap;
                    q0  = fmaf(c * invD, c, q0);
                    qcd = fmaf(c * invD, dd, qcd);
                    q2  = fmaf(dd * invD, dd, q2);
                    float Astep = p * fmaf(-W, U, 1.0f);
                    Bp = fmaf(Astep, Bp, W * yv[e]);
                    Ap = Astep * Ap;
                    w  = e2 * fmaf(p2, w, inv_sigma2 * omp2) * invD;
                }
            }
        } else {
            for (int i = start; i < end; ++i) {
                float ti = __ldg(t + i);
                int   b  = __ldg(band + i);
                float yi = __ldg(y + i);
                float ye = __ldg(yerr + i);
                float u  = pick_amp(b, a1, a2, a3);
                float U  = sigma2 * u;
                float e2 = ye * ye;
                float dt = ti - prev_t;
                prev_t = ti;
                float p    = (i == 0) ? 0.0f : __expf(nie * dt);
                float omp2 = (i == 0) ? 1.0f : -expm1f(two_nie * dt);
                float p2   = 1.0f - omp2;
                float Dt   = fmaf(U * u, omp2, e2);
                float D    = fmaf(U * U * p2, w, Dt);
                float invD = fast_rcp(D);
                float W    = fmaf(U * p2, w, u * omp2) * invD;
                ld += __logf(D);
                float Up = U * p;
                float c  = fmaf(-Up, Bp, yi);
                float dd = Up * Ap;
                q0  = fmaf(c * invD, c, q0);
                qcd = fmaf(c * invD, dd, qcd);
                q2  = fmaf(dd * invD, dd, q2);
                float Astep = p * fmaf(-W, U, 1.0f);
                Bp = fmaf(Astep, Bp, W * yi);
                Ap = Astep * Ap;
                w  = e2 * fmaf(p2, w, inv_sigma2 * omp2) * invD;
            }
        }
        g_segQ[seg] = make_float4(q0, qcd, q2, 0.f);
    }

    // in-block affine scan
    block_scan_aff(make_float2(Ap, Bp), sa, wb2, tid);
    if (seg < nseg)
        g_segPrefA[seg] = (tid == 0) ? make_float2(1.f, 0.f) : sa[tid - 1];
    if (tid == TPB - 1) g_blockA[blockIdx.x] = sa[tid];

    sd[tid] = (double)ld;
    __syncthreads();
    #pragma unroll
    for (int s = TPB / 2; s > 0; s >>= 1) {
        if (tid < s) sd[tid] += sd[tid + s];
        __syncthreads();
    }
    if (tid == 0) g_partLd[blockIdx.x] = sd[0];
}

// ------------------- kE: affine block-prefix recompute + quad + final --------
__global__ void __launch_bounds__(TPB) kE_quad(float* __restrict__ out, int N, int nseg, int nblk)
{
    __shared__ float2 sa[TPB];
    __shared__ float2 wb2[NWARP];
    __shared__ double sd[TPB];
    __shared__ bool s_last;
    int tid = threadIdx.x;
    int seg = blockIdx.x * TPB + tid;

    // --- redundant scan of block affine composites ---
    int C = (nblk + TPB - 1) / TPB;
    {
        float2 r = make_float2(1.f, 0.f);
        int s0 = tid * C, s1 = min(s0 + C, nblk);
        for (int k = s0; k < s1; ++k) r = aff_mul(g_blockA[k], r);
        block_scan_aff(r, sa, wb2, tid);
    }
    float cgblk = 0.f;   // cg entering this block (cg0 = 0)
    {
        int bq = blockIdx.x / C;
        int br = blockIdx.x % C;
        float2 mb = make_float2(1.f, 0.f);
        if (bq > 0) mb = sa[bq - 1];
        int s0 = bq * C;
        for (int k = s0; k < s0 + br; ++k) mb = aff_mul(g_blockA[k], mb);
        cgblk = mb.y;
    }
    __syncthreads();

    float contrib = 0.f;
    if (seg < nseg) {
        float2 pr = g_segPrefA[seg];
        float cg = fmaf(pr.x, cgblk, pr.y);
        float4 q = g_segQ[seg];
        contrib = fmaf(q.z * cg - 2.0f * q.y, cg, q.x);
    }
    sd[tid] = (double)contrib;
    __syncthreads();
    #pragma unroll
    for (int s = TPB / 2; s > 0; s >>= 1) {
        if (tid < s) sd[tid] += sd[tid + s];
        __syncthreads();
    }
    if (tid == 0) {
        g_partQ[blockIdx.x] = sd[0];
        __threadfence();
        int prev = atomicAdd(&g_done, 1);
        s_last = (prev == gridDim.x - 1);
    }
    __syncthreads();

    if (s_last) {
        double acc = 0.0;
        for (int k = tid; k < nblk; k += TPB) acc += g_partLd[k] + g_partQ[k];
        sd[tid] = acc;
        __syncthreads();
        #pragma unroll
        for (int s = TPB / 2; s > 0; s >>= 1) {
            if (tid < s) sd[tid] += sd[tid + s];
            __syncthreads();
        }
        if (tid == 0) {
            double total = sd[0] + (double)N * 1.837877066409345483560659472811;
            out[0] = (float)(-0.5 * total);
            atomicExch(&g_done, 0);   // self-reset for graph replay
        }
    }
}

extern "C" void kernel_launch(void* const* d_in, const int* in_sizes, int n_in,
                              void* d_out, int out_size)
{
    const float* t    = (const float*)d_in[0];
    const int*   band = (const int*)  d_in[1];
    const float* y    = (const float*)d_in[2];
    const float* yerr = (const float*)d_in[3];
    const float* lad  = (const float*)d_in[4];
    const float* lkp  = (const float*)d_in[5];
    float* out = (float*)d_out;

    int N = in_sizes[0];
    int nseg = (N + SEG_LEN - 1) / SEG_LEN;
    int nblk = (nseg + TPB - 1) / TPB;

    kA_mobius<<<nblk, TPB>>>(t, band, yerr, lad, lkp, N, nseg);
    kC_seg<<<nblk, TPB>>>(t, band, y, yerr, lad, lkp, N, nseg, nblk);
    kE_quad<<<nblk, TPB>>>(out, N, nseg, nblk);
}